// round 1
// baseline (speedup 1.0000x reference)
#include <cuda_runtime.h>

#define MDIM 12288
#define CIN 8
#define COUT 16
#define KTAP 5
#define TJ 512            // j-tile (columns of L) staged in smem
#define RPW 4             // rows of L per warp
#define NW 8              // warps per block
#define RPB (RPW * NW)    // 32 rows per block
#define NBLOCKS (MDIM / RPB)  // 384

// Scratch panels for L^1 x .. L^4 x, each [CIN][MDIM]. 1.57 MB total.
__device__ __align__(16) float g_pan[KTAP - 1][CIN * MDIM];

// next[i][m] = sum_j L[m][j] * cur[i][j]
__global__ __launch_bounds__(256, 3)
void step_kernel(const float* __restrict__ L,
                 const float* __restrict__ cur,
                 float* __restrict__ nxt) {
    __shared__ float4 sc4[CIN][TJ / 4];

    const int tid  = threadIdx.x;
    const int lane = tid & 31;
    const int w    = tid >> 5;
    const int m0   = blockIdx.x * RPB + w * RPW;

    float acc[RPW][CIN];
#pragma unroll
    for (int r = 0; r < RPW; ++r)
#pragma unroll
        for (int i = 0; i < CIN; ++i) acc[r][i] = 0.0f;

    const float4* cur4 = reinterpret_cast<const float4*>(cur);

    for (int jb = 0; jb < MDIM; jb += TJ) {
        // Cooperative stage of the panel tile: CIN x TJ floats = 1024 float4.
#pragma unroll
        for (int t = 0; t < (CIN * TJ / 4) / 256; ++t) {
            int idx = t * 256 + tid;
            int i   = idx >> 7;       // / (TJ/4 = 128)
            int off = idx & 127;
            sc4[i][off] = cur4[(size_t)i * (MDIM / 4) + (jb >> 2) + off];
        }
        __syncthreads();

#pragma unroll
        for (int s = 0; s < TJ / 128; ++s) {
            const int c = s * 32 + lane;     // float4 index within tile
            float4 a[RPW];
#pragma unroll
            for (int r = 0; r < RPW; ++r)
                a[r] = reinterpret_cast<const float4*>(
                           L + (size_t)(m0 + r) * MDIM + jb)[c];
#pragma unroll
            for (int i = 0; i < CIN; ++i) {
                float4 b = sc4[i][c];
#pragma unroll
                for (int r = 0; r < RPW; ++r) {
                    acc[r][i] += a[r].x * b.x;
                    acc[r][i] += a[r].y * b.y;
                    acc[r][i] += a[r].z * b.z;
                    acc[r][i] += a[r].w * b.w;
                }
            }
        }
        __syncthreads();
    }

    // Warp-wide reduction (lanes covered disjoint j), then store.
#pragma unroll
    for (int r = 0; r < RPW; ++r)
#pragma unroll
        for (int i = 0; i < CIN; ++i) {
            float v = acc[r][i];
            v += __shfl_down_sync(0xffffffffu, v, 16);
            v += __shfl_down_sync(0xffffffffu, v, 8);
            v += __shfl_down_sync(0xffffffffu, v, 4);
            v += __shfl_down_sync(0xffffffffu, v, 2);
            v += __shfl_down_sync(0xffffffffu, v, 1);
            if (lane == 0) nxt[(size_t)i * MDIM + m0 + r] = v;
        }
}

// y[o][m] = bias[o] + sum_{i,k} theta[o][i][k] * P[k][i][m]
__global__ __launch_bounds__(256)
void mix_kernel(const float* __restrict__ x,
                const float* __restrict__ theta,
                const float* __restrict__ bias,
                float* __restrict__ out) {
    __shared__ float th[COUT * CIN * KTAP];
    __shared__ float bs[COUT];
    const int tid = threadIdx.x;
    for (int idx = tid; idx < COUT * CIN * KTAP; idx += blockDim.x)
        th[idx] = theta[idx];
    if (tid < COUT) bs[tid] = bias[tid];
    __syncthreads();

    const int m = blockIdx.x * blockDim.x + tid;
    if (m >= MDIM) return;

    float p[KTAP][CIN];
#pragma unroll
    for (int i = 0; i < CIN; ++i) p[0][i] = x[(size_t)i * MDIM + m];
#pragma unroll
    for (int k = 1; k < KTAP; ++k)
#pragma unroll
        for (int i = 0; i < CIN; ++i)
            p[k][i] = g_pan[k - 1][i * MDIM + m];

#pragma unroll
    for (int o = 0; o < COUT; ++o) {
        float s = bs[o];
#pragma unroll
        for (int i = 0; i < CIN; ++i)
#pragma unroll
            for (int k = 0; k < KTAP; ++k)
                s += th[(o * CIN + i) * KTAP + k] * p[k][i];
        out[(size_t)o * MDIM + m] = s;
    }
}

extern "C" void kernel_launch(void* const* d_in, const int* in_sizes, int n_in,
                              void* d_out, int out_size) {
    const float* L     = (const float*)d_in[0];
    const float* x     = (const float*)d_in[1];
    const float* theta = (const float*)d_in[2];
    const float* bias  = (const float*)d_in[3];
    float* out = (float*)d_out;

    float* pan = nullptr;
    cudaGetSymbolAddress((void**)&pan, g_pan);  // host-side query; not a stream op

    const size_t PSZ = (size_t)CIN * MDIM;

    step_kernel<<<NBLOCKS, 256>>>(L, x,             pan + 0 * PSZ);
    step_kernel<<<NBLOCKS, 256>>>(L, pan + 0 * PSZ, pan + 1 * PSZ);
    step_kernel<<<NBLOCKS, 256>>>(L, pan + 1 * PSZ, pan + 2 * PSZ);
    step_kernel<<<NBLOCKS, 256>>>(L, pan + 2 * PSZ, pan + 3 * PSZ);

    mix_kernel<<<(MDIM + 255) / 256, 256>>>(x, theta, bias, out);
}

// round 2
// speedup vs baseline: 1.0437x; 1.0437x over previous
#include <cuda_runtime.h>
#include <cstdint>

#define MDIM 12288
#define CIN 8
#define NPAIR 4           // channel pairs (CIN/2)
#define COUT 16
#define KTAP 5
#define TJ 512            // j-tile staged in smem
#define RPW 4             // rows of L per warp
#define NW 8              // warps per block
#define RPB (RPW * NW)    // 32 rows per block
#define NBLOCKS (MDIM / RPB)  // 384

// 128B-row swizzle (Swizzle<3,4,3>): XOR bits[7:10) into [4:7). Keeps >=16B alignment.
#define SWZ(b) ((b) ^ (((b) >> 3) & 0x70))

// Scratch panels for L^1 x .. L^4 x, each [CIN][MDIM].
__device__ __align__(16) float g_pan[KTAP - 1][CIN * MDIM];

__device__ __forceinline__ unsigned long long pack2(float lo, float hi) {
    unsigned long long r;
    asm("mov.b64 %0, {%1, %2};" : "=l"(r) : "f"(lo), "f"(hi));
    return r;
}
__device__ __forceinline__ void unpack2(unsigned long long v, float& lo, float& hi) {
    asm("mov.b64 {%0, %1}, %2;" : "=f"(lo), "=f"(hi) : "l"(v));
}
__device__ __forceinline__ void fma2(unsigned long long& acc,
                                     unsigned long long a, unsigned long long b) {
    asm("fma.rn.f32x2 %0, %1, %2, %0;" : "+l"(acc) : "l"(a), "l"(b));
}

// next[i][m] = sum_j L[m][j] * cur[i][j], channels packed in f32x2 pairs.
__global__ __launch_bounds__(256, 3)
void step_kernel(const float* __restrict__ L,
                 const float* __restrict__ cur,
                 float* __restrict__ nxt) {
    // Panel tile: for each tile-local column j, 4 channel-pairs (8B each) = 32B/column.
    __shared__ __align__(16) unsigned char sp[TJ * NPAIR * 8];   // 16 KB

    const int tid  = threadIdx.x;
    const int lane = tid & 31;
    const int w    = tid >> 5;
    const int m0   = blockIdx.x * RPB + w * RPW;

    unsigned long long acc[RPW][NPAIR];
#pragma unroll
    for (int r = 0; r < RPW; ++r)
#pragma unroll
        for (int p = 0; p < NPAIR; ++p) acc[r][p] = 0ull;

    for (int jb = 0; jb < MDIM; jb += TJ) {
        // Stage panel tile as channel-pair interleaved, swizzled.
#pragma unroll
        for (int it = 0; it < (TJ * NPAIR) / 256; ++it) {      // 8 iters
            int idx = it * 256 + tid;
            int j   = idx & (TJ - 1);
            int p   = idx >> 9;                                 // 0..3
            unsigned long long v =
                pack2(cur[(size_t)(2 * p) * MDIM + jb + j],
                      cur[(size_t)(2 * p + 1) * MDIM + jb + j]);
            *reinterpret_cast<unsigned long long*>(sp + SWZ(j * 32 + p * 8)) = v;
        }
        __syncthreads();

#pragma unroll
        for (int s = 0; s < TJ / 128; ++s) {
            const int c = s * 32 + lane;                        // float4 index in tile
            float4 a[RPW];
#pragma unroll
            for (int r = 0; r < RPW; ++r)
                a[r] = __ldcs(reinterpret_cast<const float4*>(
                           L + (size_t)(m0 + r) * MDIM + jb) + c);
#pragma unroll
            for (int jj = 0; jj < 4; ++jj) {
                const int jl = 4 * c + jj;                      // tile-local column
                ulonglong2 q0 = *reinterpret_cast<const ulonglong2*>(sp + SWZ(jl * 32));
                ulonglong2 q1 = *reinterpret_cast<const ulonglong2*>(sp + SWZ(jl * 32 + 16));
#pragma unroll
                for (int r = 0; r < RPW; ++r) {
                    float av = (jj == 0) ? a[r].x : (jj == 1) ? a[r].y
                             : (jj == 2) ? a[r].z : a[r].w;
                    unsigned long long aa = pack2(av, av);
                    fma2(acc[r][0], aa, q0.x);
                    fma2(acc[r][1], aa, q0.y);
                    fma2(acc[r][2], aa, q1.x);
                    fma2(acc[r][3], aa, q1.y);
                }
            }
        }
        __syncthreads();
    }

    // Warp reduction over lanes (disjoint j), then store.
#pragma unroll
    for (int r = 0; r < RPW; ++r)
#pragma unroll
        for (int p = 0; p < NPAIR; ++p) {
            float v0, v1;
            unpack2(acc[r][p], v0, v1);
#pragma unroll
            for (int d = 16; d > 0; d >>= 1) {
                v0 += __shfl_down_sync(0xffffffffu, v0, d);
                v1 += __shfl_down_sync(0xffffffffu, v1, d);
            }
            if (lane == 0) {
                nxt[(size_t)(2 * p) * MDIM + m0 + r]     = v0;
                nxt[(size_t)(2 * p + 1) * MDIM + m0 + r] = v1;
            }
        }
}

// y[o][m] = bias[o] + sum_{i,k} theta[o][i][k] * P[k][i][m]
__global__ __launch_bounds__(256)
void mix_kernel(const float* __restrict__ x,
                const float* __restrict__ theta,
                const float* __restrict__ bias,
                float* __restrict__ out) {
    __shared__ float th[COUT * CIN * KTAP];
    __shared__ float bs[COUT];
    const int tid = threadIdx.x;
    for (int idx = tid; idx < COUT * CIN * KTAP; idx += blockDim.x)
        th[idx] = theta[idx];
    if (tid < COUT) bs[tid] = bias[tid];
    __syncthreads();

    const int m = blockIdx.x * blockDim.x + tid;
    if (m >= MDIM) return;

    float p[KTAP][CIN];
#pragma unroll
    for (int i = 0; i < CIN; ++i) p[0][i] = x[(size_t)i * MDIM + m];
#pragma unroll
    for (int k = 1; k < KTAP; ++k)
#pragma unroll
        for (int i = 0; i < CIN; ++i)
            p[k][i] = g_pan[k - 1][i * MDIM + m];

#pragma unroll
    for (int o = 0; o < COUT; ++o) {
        float s = bs[o];
#pragma unroll
        for (int i = 0; i < CIN; ++i)
#pragma unroll
            for (int k = 0; k < KTAP; ++k)
                s += th[(o * CIN + i) * KTAP + k] * p[k][i];
        out[(size_t)o * MDIM + m] = s;
    }
}

extern "C" void kernel_launch(void* const* d_in, const int* in_sizes, int n_in,
                              void* d_out, int out_size) {
    const float* L     = (const float*)d_in[0];
    const float* x     = (const float*)d_in[1];
    const float* theta = (const float*)d_in[2];
    const float* bias  = (const float*)d_in[3];
    float* out = (float*)d_out;

    float* pan = nullptr;
    cudaGetSymbolAddress((void**)&pan, g_pan);

    const size_t PSZ = (size_t)CIN * MDIM;

    step_kernel<<<NBLOCKS, 256>>>(L, x,             pan + 0 * PSZ);
    step_kernel<<<NBLOCKS, 256>>>(L, pan + 0 * PSZ, pan + 1 * PSZ);
    step_kernel<<<NBLOCKS, 256>>>(L, pan + 1 * PSZ, pan + 2 * PSZ);
    step_kernel<<<NBLOCKS, 256>>>(L, pan + 2 * PSZ, pan + 3 * PSZ);

    mix_kernel<<<(MDIM + 255) / 256, 256>>>(x, theta, bias, out);
}